// round 1
// baseline (speedup 1.0000x reference)
#include <cuda_runtime.h>
#include <math.h>

// Problem: loss = mean_n [ logsumexp_m( q_n · t_m ) - q_n · t_n ]
//          q = logits - log(noise_probs), T = 1
// N = M = 16384, D = 64.

#define N_ROWS 16384
#define M_COLS 16384
#define DIM    64
#define TM     64          // rows per block
#define TN     128         // target cols per tile
#define NTILES (M_COLS / TN)   // 128
#define NBLOCKS (N_ROWS / TM)  // 256

__device__ float g_partial[NBLOCKS];

__global__ void __launch_bounds__(256)
infonce_main(const float* __restrict__ logits,
             const float* __restrict__ targets,
             const float* __restrict__ noise)
{
    // k-major shared tiles: contiguous, conflict-free inner-loop reads.
    __shared__ float q_sh[DIM][TM];   // 16 KB
    __shared__ float t_sh[DIM][TN];   // 32 KB   (total exactly 48 KB)

    const int tid  = threadIdx.x;
    const int tx   = tid & 15;    // column group: cols tx*8 .. tx*8+7
    const int ty   = tid >> 4;    // row group:    rows ty*4 .. ty*4+3
    const int row0 = blockIdx.x * TM;

    // This thread's fixed d-chunk for global loads.
    const int dchunk = tx * 4;
    float ln[4];
#pragma unroll
    for (int j = 0; j < 4; j++) ln[j] = logf(noise[dchunk + j]);

    // Load q tile (transpose into k-major), fusing q = logits - log(noise).
#pragma unroll
    for (int i = 0; i < 4; i++) {
        const int r = (tid >> 4) + 16 * i;   // 0..63
        const float4 v = *reinterpret_cast<const float4*>(
            &logits[(size_t)(row0 + r) * DIM + dchunk]);
        q_sh[dchunk + 0][r] = v.x - ln[0];
        q_sh[dchunk + 1][r] = v.y - ln[1];
        q_sh[dchunk + 2][r] = v.z - ln[2];
        q_sh[dchunk + 3][r] = v.w - ln[3];
    }

    float run_max[4], run_sum[4], diag[4];
#pragma unroll
    for (int r = 0; r < 4; r++) {
        run_max[r] = -INFINITY;
        run_sum[r] = 0.0f;
        diag[r]    = 0.0f;
    }

    // The single m-tile that contains this block's diagonal entries.
    const int diag_m0 = row0 & ~(TN - 1);

    for (int t = 0; t < NTILES; t++) {
        const int m0 = t * TN;

        __syncthreads();   // previous tile's reads done (also covers q_sh writes)

        // Load targets tile (transpose into k-major).
#pragma unroll
        for (int i = 0; i < 8; i++) {
            const int r = (tid >> 4) + 16 * i;   // 0..127
            const float4 v = *reinterpret_cast<const float4*>(
                &targets[(size_t)(m0 + r) * DIM + dchunk]);
            t_sh[dchunk + 0][r] = v.x;
            t_sh[dchunk + 1][r] = v.y;
            t_sh[dchunk + 2][r] = v.z;
            t_sh[dchunk + 3][r] = v.w;
        }
        __syncthreads();

        // 4x8 register micro-tile GEMM over k = 0..63.
        float acc[4][8];
#pragma unroll
        for (int r = 0; r < 4; r++)
#pragma unroll
            for (int c = 0; c < 8; c++) acc[r][c] = 0.0f;

#pragma unroll 8
        for (int k = 0; k < DIM; k++) {
            const float4 qv  = *reinterpret_cast<const float4*>(&q_sh[k][ty * 4]);
            const float4 tv0 = *reinterpret_cast<const float4*>(&t_sh[k][tx * 8]);
            const float4 tv1 = *reinterpret_cast<const float4*>(&t_sh[k][tx * 8 + 4]);
            const float qa[4] = {qv.x, qv.y, qv.z, qv.w};
            const float tb[8] = {tv0.x, tv0.y, tv0.z, tv0.w,
                                 tv1.x, tv1.y, tv1.z, tv1.w};
#pragma unroll
            for (int r = 0; r < 4; r++)
#pragma unroll
                for (int c = 0; c < 8; c++)
                    acc[r][c] = fmaf(qa[r], tb[c], acc[r][c]);
        }

        // Capture diagonal scores (block-uniform branch; one tile per block).
        if (m0 == diag_m0) {
#pragma unroll
            for (int r = 0; r < 4; r++) {
                const int lc = (row0 + ty * 4 + r) - m0 - tx * 8;
#pragma unroll
                for (int c = 0; c < 8; c++)
                    if (lc == c) diag[r] = acc[r][c];
            }
            // Broadcast within the 16-lane row group (only the owning lane
            // captured a value; the rest hold 0, so a sum-reduce works).
#pragma unroll
            for (int r = 0; r < 4; r++)
#pragma unroll
                for (int o = 1; o < 16; o <<= 1)
                    diag[r] += __shfl_xor_sync(0xffffffffu, diag[r], o);
        }

        // Online softmax update (per row; 16-lane shfl reductions).
#pragma unroll
        for (int r = 0; r < 4; r++) {
            float m = acc[r][0];
#pragma unroll
            for (int c = 1; c < 8; c++) m = fmaxf(m, acc[r][c]);
#pragma unroll
            for (int o = 1; o < 16; o <<= 1)
                m = fmaxf(m, __shfl_xor_sync(0xffffffffu, m, o));

            const float nm = fmaxf(run_max[r], m);
            float s = 0.0f;
#pragma unroll
            for (int c = 0; c < 8; c++) s += __expf(acc[r][c] - nm);
#pragma unroll
            for (int o = 1; o < 16; o <<= 1)
                s += __shfl_xor_sync(0xffffffffu, s, o);

            run_sum[r] = run_sum[r] * __expf(run_max[r] - nm) + s;
            run_max[r] = nm;
        }
    }

    // Block reduction of per-row loss contributions.
    __syncthreads();                 // done reading q_sh; reuse as scratch
    float* red = &q_sh[0][0];
    if (tx == 0) {
        float v = 0.0f;
#pragma unroll
        for (int r = 0; r < 4; r++)
            v += run_max[r] + logf(run_sum[r]) - diag[r];
        red[ty] = v;
    }
    __syncthreads();
    if (tid == 0) {
        float v = 0.0f;
#pragma unroll
        for (int i = 0; i < 16; i++) v += red[i];
        g_partial[blockIdx.x] = v;
    }
}

__global__ void infonce_finalize(float* __restrict__ out)
{
    __shared__ float s[NBLOCKS];
    s[threadIdx.x] = g_partial[threadIdx.x];
    __syncthreads();
#pragma unroll
    for (int st = NBLOCKS / 2; st > 0; st >>= 1) {
        if ((int)threadIdx.x < st) s[threadIdx.x] += s[threadIdx.x + st];
        __syncthreads();
    }
    if (threadIdx.x == 0) out[0] = s[0] / (float)N_ROWS;
}

extern "C" void kernel_launch(void* const* d_in, const int* in_sizes, int n_in,
                              void* d_out, int out_size)
{
    const float* logits  = (const float*)d_in[0];
    const float* targets = (const float*)d_in[1];
    const float* noise   = (const float*)d_in[2];

    infonce_main<<<NBLOCKS, 256>>>(logits, targets, noise);
    infonce_finalize<<<1, NBLOCKS>>>((float*)d_out);
}

// round 3
// speedup vs baseline: 2.1247x; 2.1247x over previous
#include <cuda_runtime.h>
#include <cuda_bf16.h>
#include <math.h>
#include <stdint.h>

// loss = mean_n [ logsumexp_m( q_n . t_m ) - q_n . t_n ],  q = logits - log(noise)
// N = M = 16384, D = 64.
// GEMM on tensor pipe via base-ISA mma.sync (bf16 hi/lo split, 3 terms),
// online softmax fused on register fragments. No tcgen05 (harness compiles
// at virtual arch compute_103, which forbids 'a'-suffix features).

#define NTOT    16384
#define DIM     64
#define TM      128                 // q rows per block
#define TN      128                 // target rows per tile iteration
#define NTILES  (NTOT / TN)         // 128
#define NBLOCKS (NTOT / TM)         // 128

// Pre-split, chunk-swizzled bf16 images of targets (128 B per row).
__device__ __align__(128) unsigned char g_thi[(size_t)NTOT * 128];
__device__ __align__(128) unsigned char g_tlo[(size_t)NTOT * 128];
__device__ float g_partial[NBLOCKS];

// ---------------- PTX helpers ----------------
static __device__ __forceinline__ uint32_t smem_u32(const void* p) {
    uint32_t a;
    asm("{ .reg .u64 t; cvta.to.shared.u64 t, %1; cvt.u32.u64 %0, t; }"
        : "=r"(a) : "l"(p));
    return a;
}
#define MBAR_INIT(a, c) \
    asm volatile("mbarrier.init.shared.b64 [%0], %1;" :: "r"(a), "r"(c) : "memory")
#define MBAR_EXPECT(a, b) \
    asm volatile("mbarrier.arrive.expect_tx.shared.b64 _, [%0], %1;" :: "r"(a), "r"(b) : "memory")
#define MBAR_WAIT(a, ph) do {                                                        \
    uint32_t _m = (a), _p = (ph), _d;                                                \
    asm volatile("{ .reg .pred p; mbarrier.try_wait.parity.acquire.cta.shared::cta.b64 p, [%1], %2; selp.b32 %0,1,0,p; }" \
                 : "=r"(_d) : "r"(_m), "r"(_p) : "memory");                          \
    if (!_d) {                                                                       \
        asm volatile("{ .reg .pred P1; WL%=: mbarrier.try_wait.parity.acquire.cta.shared::cta.b64 P1, [%0], %1, 0x989680; @P1 bra.uni WD%=; bra.uni WL%=; WD%=: }" \
                     :: "r"(_m), "r"(_p) : "memory");                                \
    }                                                                                \
} while (0)

static __device__ __forceinline__ void bulk_g2s(uint32_t dst, const void* src,
                                                uint32_t bytes, uint32_t mbar) {
    uint64_t g;
    asm("cvta.to.global.u64 %0, %1;" : "=l"(g) : "l"(src));
    asm volatile("cp.async.bulk.shared::cta.global.mbarrier::complete_tx::bytes [%0], [%1], %2, [%3];"
                 :: "r"(dst), "l"(g), "r"(bytes), "r"(mbar) : "memory");
}

#define LDSM4(r, a) \
    asm volatile("ldmatrix.sync.aligned.m8n8.x4.shared.b16 {%0,%1,%2,%3}, [%4];" \
                 : "=r"((r)[0]), "=r"((r)[1]), "=r"((r)[2]), "=r"((r)[3]) : "r"(a))

#define MMA16816(d, a, b0, b1) \
    asm volatile("mma.sync.aligned.m16n8k16.row.col.f32.bf16.bf16.f32 " \
                 "{%0,%1,%2,%3}, {%4,%5,%6,%7}, {%8,%9}, {%0,%1,%2,%3};" \
                 : "+f"((d)[0]), "+f"((d)[1]), "+f"((d)[2]), "+f"((d)[3]) \
                 : "r"((a)[0]), "r"((a)[1]), "r"((a)[2]), "r"((a)[3]), \
                   "r"(b0), "r"(b1))

// ---- hi/lo bf16 split of 8 fp32 values, packed to two uint4 ----
static __device__ __forceinline__ void split8(const float* x, uint4& uh, uint4& ul) {
    uint32_t h[8], l[8];
#pragma unroll
    for (int j = 0; j < 8; j++) {
        __nv_bfloat16 bh = __float2bfloat16(x[j]);
        float r = x[j] - __bfloat162float(bh);
        __nv_bfloat16 bl = __float2bfloat16(r);
        h[j] = (uint32_t)__bfloat16_as_ushort(bh);
        l[j] = (uint32_t)__bfloat16_as_ushort(bl);
    }
    uh = make_uint4(h[0] | (h[1] << 16), h[2] | (h[3] << 16),
                    h[4] | (h[5] << 16), h[6] | (h[7] << 16));
    ul = make_uint4(l[0] | (l[1] << 16), l[2] | (l[3] << 16),
                    l[4] | (l[5] << 16), l[6] | (l[7] << 16));
}

// ---------------- prep: split + swizzle targets into global images ----------------
// Element (row, k) lives at byte row*128 + ((chunk ^ (row&7))*16) + (k&7)*2,
// chunk = k>>3. Same layout ldmatrix addresses expect (conflict-free).
__global__ void __launch_bounds__(256) prep_targets(const float* __restrict__ tg) {
    int idx = blockIdx.x * 256 + threadIdx.x;   // 16384*8 chunks of 8 elems
    int row = idx >> 3, c = idx & 7;
    const float4* p = reinterpret_cast<const float4*>(tg + (size_t)row * DIM + c * 8);
    float4 a = p[0], b = p[1];
    float x[8] = {a.x, a.y, a.z, a.w, b.x, b.y, b.z, b.w};
    uint4 uh, ul;
    split8(x, uh, ul);
    int slot = row * 8 + (c ^ (row & 7));
    reinterpret_cast<uint4*>(g_thi)[slot] = uh;
    reinterpret_cast<uint4*>(g_tlo)[slot] = ul;
}

// ---------------- main fused kernel ----------------
// SMEM: [0,16K) q_hi, [16K,32K) q_lo,
//       [32K + s*32K): tile buffer s = { t_hi 16K, t_lo 16K },  s = 0,1
//       [96K): mbarriers
#define QHI   0u
#define QLO   16384u
#define TBUF(s) (32768u + (uint32_t)(s) * 32768u)
#define BARO  98304u
#define SMEM_BYTES (98304 + 64)

__global__ void __launch_bounds__(256, 1)
infonce_mma(const float* __restrict__ logits, const float* __restrict__ noise) {
    extern __shared__ unsigned char smem[];
    const uint32_t sb = smem_u32(smem);
    const int tid = threadIdx.x, wid = tid >> 5, lane = tid & 31;
    const int b = blockIdx.x;

    const uint32_t bar0 = sb + BARO, bar1 = sb + BARO + 8;
    if (tid == 0) { MBAR_INIT(bar0, 1); MBAR_INIT(bar1, 1); }

    // ---- q prologue: q = logits - log(noise); split hi/lo; swizzled STS ----
#pragma unroll
    for (int i = 0; i < 4; i++) {
        int ch = tid + 256 * i;                 // 0..1023 (128 rows x 8 chunks)
        int row = ch >> 3, c = ch & 7;
        const float4* p = reinterpret_cast<const float4*>(
            logits + (size_t)(b * TM + row) * DIM + c * 8);
        float4 a = p[0], bb = p[1];
        float x[8] = {a.x, a.y, a.z, a.w, bb.x, bb.y, bb.z, bb.w};
#pragma unroll
        for (int j = 0; j < 8; j++) x[j] -= logf(noise[c * 8 + j]);
        uint4 uh, ul;
        split8(x, uh, ul);
        uint32_t off = (uint32_t)row * 128u + (uint32_t)((c ^ (row & 7)) * 16);
        *reinterpret_cast<uint4*>(smem + QHI + off) = uh;
        *reinterpret_cast<uint4*>(smem + QLO + off) = ul;
    }

    // prefetch tiles 0 and 1
    if (tid == 0) {
        MBAR_EXPECT(bar0, 32768);
        bulk_g2s(sb + TBUF(0),          g_thi,         16384, bar0);
        bulk_g2s(sb + TBUF(0) + 16384u, g_tlo,         16384, bar0);
        MBAR_EXPECT(bar1, 32768);
        bulk_g2s(sb + TBUF(1),          g_thi + 16384, 16384, bar1);
        bulk_g2s(sb + TBUF(1) + 16384u, g_tlo + 16384, 16384, bar1);
    }
    __syncthreads();   // q_sh visible to all warps

    // warp tiling: 4 row-groups x 2 col-groups; warp = 32 rows x 64 cols
    const int wr = wid & 3, wc = wid >> 2;
    // ldmatrix lane decomposition
    const int lrow  = (lane & 7) + ((lane >> 3) & 1) * 8;  // row within 16-tile
    const int lchk  = lane >> 4;                           // chunk add (0/1)
    const int swrow = lane & 7;                            // row&7 for swizzle

    const uint32_t a_base = sb + QHI + (uint32_t)(wr * 32 + lrow) * 128u;

    float run_max[4], run_sum[4], diagv[4];
#pragma unroll
    for (int j = 0; j < 4; j++) {
        run_max[j] = -INFINITY; run_sum[j] = 0.0f; diagv[j] = 0.0f;
    }

    for (int t = 0; t < NTILES; t++) {
        const int s = t & 1;
        MBAR_WAIT((s ? bar1 : bar0), (t >> 1) & 1);

        float acc[2][8][4];
#pragma unroll
        for (int at = 0; at < 2; at++)
#pragma unroll
            for (int nt = 0; nt < 8; nt++)
#pragma unroll
                for (int e = 0; e < 4; e++) acc[at][nt][e] = 0.0f;

        const uint32_t th_base = sb + TBUF(s) +
                                 (uint32_t)(wc * 64 + lrow) * 128u;

#pragma unroll
        for (int k = 0; k < 4; k++) {
            const uint32_t sw = (uint32_t)(((k * 2 + lchk) ^ swrow) << 4);

            uint32_t AH[2][4], AL[2][4];
#pragma unroll
            for (int at = 0; at < 2; at++) {
                uint32_t aa = a_base + (uint32_t)(at * 2048) + sw;
                LDSM4(AH[at], aa);
                LDSM4(AL[at], aa + 16384u);
            }
            uint32_t BH[4][4], BL[4][4];
#pragma unroll
            for (int g = 0; g < 4; g++) {
                uint32_t ba = th_base + (uint32_t)(g * 2048) + sw;
                LDSM4(BH[g], ba);
                LDSM4(BL[g], ba + 16384u);
            }
#pragma unroll
            for (int at = 0; at < 2; at++) {
#pragma unroll
                for (int nt = 0; nt < 8; nt++) {
                    const int g = nt >> 1, su = nt & 1;
                    MMA16816(acc[at][nt], AH[at], BH[g][su], BH[g][2 + su]);
                    MMA16816(acc[at][nt], AH[at], BL[g][su], BL[g][2 + su]);
                    MMA16816(acc[at][nt], AL[at], BH[g][su], BH[g][2 + su]);
                }
            }
        }

        // all warps done reading buffer s -> refill with tile t+2
        __syncthreads();
        if (t + 2 < NTILES && tid == 0) {
            const uint32_t tb = s ? bar1 : bar0;
            MBAR_EXPECT(tb, 32768);
            bulk_g2s(sb + TBUF(s),          g_thi + (size_t)(t + 2) * 16384, 16384, tb);
            bulk_g2s(sb + TBUF(s) + 16384u, g_tlo + (size_t)(t + 2) * 16384, 16384, tb);
        }

        // ---- diagonal extraction (tile t == blockIdx.x holds the diagonal) ----
        if (t == b) {
#pragma unroll
            for (int j = 0; j < 4; j++) {
                const int rloc = wr * 32 + (j >> 1) * 16 + (j & 1) * 8 + (lane >> 2);
                const int cw = rloc - wc * 64;
                if (cw >= 0 && cw < 64) {
                    const int nt = cw >> 3;
                    if (((cw >> 1) & 3) == (lane & 3))
                        diagv[j] = acc[j >> 1][nt][(j & 1) * 2 + (cw & 1)];
                }
            }
        }

        // ---- online softmax on fragments (quad-wide rows) ----
#pragma unroll
        for (int j = 0; j < 4; j++) {
            const int at = j >> 1, er = (j & 1) * 2;
            float v[16];
#pragma unroll
            for (int nt = 0; nt < 8; nt++) {
                v[nt * 2]     = acc[at][nt][er];
                v[nt * 2 + 1] = acc[at][nt][er + 1];
            }
            float m8[8];
#pragma unroll
            for (int i = 0; i < 8; i++) m8[i] = fmaxf(v[i], v[i + 8]);
#pragma unroll
            for (int w = 4; w > 0; w >>= 1)
#pragma unroll
                for (int i = 0; i < w; i++) m8[i] = fmaxf(m8[i], m8[i + w]);
            float m = m8[0];
            m = fmaxf(m, __shfl_xor_sync(0xffffffffu, m, 1));
            m = fmaxf(m, __shfl_xor_sync(0xffffffffu, m, 2));
            const float nm = fmaxf(run_max[j], m);

            float s0 = 0.f, s1 = 0.f, s2 = 0.f, s3 = 0.f;
#pragma unroll
            for (int i = 0; i < 16; i += 4) {
                s0 += __expf(v[i + 0] - nm);
                s1 += __expf(v[i + 1] - nm);
                s2 += __expf(v[i + 2] - nm);
                s3 += __expf(v[i + 3] - nm);
            }
            float ss = (s0 + s1) + (s2 + s3);
            ss += __shfl_xor_sync(0xffffffffu, ss, 1);
            ss += __shfl_xor_sync(0xffffffffu, ss, 2);

            run_sum[j] = run_sum[j] * __expf(run_max[j] - nm) + ss;
            run_max[j] = nm;
        }
    }

    // ---- merge col-halves + block reduce ----
    __syncthreads();
    float* S = reinterpret_cast<float*>(smem);   // [0,256) max, [256,512) sum, [512,768) diag

    // quad-reduce diag (owner lane may be any lane in the quad)
#pragma unroll
    for (int j = 0; j < 4; j++) {
        float d = diagv[j];
        d += __shfl_xor_sync(0xffffffffu, d, 1);
        d += __shfl_xor_sync(0xffffffffu, d, 2);
        diagv[j] = d;
    }
    if ((lane & 3) == 0) {
#pragma unroll
        for (int j = 0; j < 4; j++) {
            const int r = wr * 32 + (j >> 1) * 16 + (j & 1) * 8 + (lane >> 2);
            S[wc * 128 + r]       = run_max[j];
            S[256 + wc * 128 + r] = run_sum[j];
            S[512 + wc * 128 + r] = diagv[j];
        }
    }
    __syncthreads();

    float loss = 0.0f;
    if (tid < 128) {
        const float m0 = S[tid],       s0 = S[256 + tid], d0 = S[512 + tid];
        const float m1 = S[128 + tid], s1 = S[384 + tid], d1 = S[640 + tid];
        const float m = fmaxf(m0, m1);
        const float ssum = s0 * __expf(m0 - m) + s1 * __expf(m1 - m);
        loss = m + logf(ssum) - (d0 + d1);
    }
#pragma unroll
    for (int o = 16; o > 0; o >>= 1)
        loss += __shfl_xor_sync(0xffffffffu, loss, o);
    __syncthreads();
    if (lane == 0) S[768 + wid] = loss;
    __syncthreads();
    if (tid == 0) {
        float v = 0.0f;
#pragma unroll
        for (int i = 0; i < 8; i++) v += S[768 + i];
        g_partial[b] = v;
    }
}

__global__ void infonce_finalize(float* __restrict__ out) {
    __shared__ float s[NBLOCKS];
    int t = threadIdx.x;
    s[t] = g_partial[t];
    __syncthreads();
#pragma unroll
    for (int st = NBLOCKS / 2; st > 0; st >>= 1) {
        if (t < st) s[t] += s[t + st];
        __syncthreads();
    }
    if (t == 0) out[0] = s[0] / (float)NTOT;
}

extern "C" void kernel_launch(void* const* d_in, const int* in_sizes, int n_in,
                              void* d_out, int out_size) {
    const float* logits  = (const float*)d_in[0];
    const float* targets = (const float*)d_in[1];
    const float* noise   = (const float*)d_in[2];

    cudaFuncSetAttribute(infonce_mma, cudaFuncAttributeMaxDynamicSharedMemorySize, SMEM_BYTES);

    prep_targets<<<NTOT * 8 / 256, 256>>>(targets);
    infonce_mma<<<NBLOCKS, 256, SMEM_BYTES>>>(logits, noise);
    infonce_finalize<<<1, NBLOCKS>>>((float*)d_out);
}

// round 4
// speedup vs baseline: 2.4046x; 1.1317x over previous
#include <cuda_runtime.h>
#include <cuda_bf16.h>
#include <math.h>
#include <stdint.h>

// loss = mean_n [ logsumexp_m( q_n . t_m ) - q_n . t_n ],  q = logits - log(noise)
// N = M = 16384, D = 64.
// GEMM on tensor pipe via base-ISA mma.sync (bf16 hi/lo split, 3 terms),
// online softmax fused on register fragments with adaptive exp skipping
// (groups > 13 below the running max are dropped; bias < 1e-5 of the sum).

#define NTOT    16384
#define DIM     64
#define TM      128                 // q rows per block
#define TN      128                 // target rows per tile iteration
#define NTILES  (NTOT / TN)         // 128
#define NBLOCKS (NTOT / TM)         // 128
#define SKIP_THRESH 13.0f

// Pre-split, chunk-swizzled bf16 images of targets (128 B per row).
__device__ __align__(128) unsigned char g_thi[(size_t)NTOT * 128];
__device__ __align__(128) unsigned char g_tlo[(size_t)NTOT * 128];
__device__ float g_partial[NBLOCKS];
__device__ unsigned int g_done;     // zero-initialized; reset by last block

// ---------------- PTX helpers ----------------
static __device__ __forceinline__ uint32_t smem_u32(const void* p) {
    uint32_t a;
    asm("{ .reg .u64 t; cvta.to.shared.u64 t, %1; cvt.u32.u64 %0, t; }"
        : "=r"(a) : "l"(p));
    return a;
}
#define MBAR_INIT(a, c) \
    asm volatile("mbarrier.init.shared.b64 [%0], %1;" :: "r"(a), "r"(c) : "memory")
#define MBAR_EXPECT(a, b) \
    asm volatile("mbarrier.arrive.expect_tx.shared.b64 _, [%0], %1;" :: "r"(a), "r"(b) : "memory")
#define MBAR_ARRIVE(a) \
    asm volatile("mbarrier.arrive.shared.b64 _, [%0];" :: "r"(a) : "memory")
#define MBAR_WAIT(a, ph) do {                                                        \
    uint32_t _m = (a), _p = (ph), _d;                                                \
    asm volatile("{ .reg .pred p; mbarrier.try_wait.parity.acquire.cta.shared::cta.b64 p, [%1], %2; selp.b32 %0,1,0,p; }" \
                 : "=r"(_d) : "r"(_m), "r"(_p) : "memory");                          \
    if (!_d) {                                                                       \
        asm volatile("{ .reg .pred P1; WL%=: mbarrier.try_wait.parity.acquire.cta.shared::cta.b64 P1, [%0], %1, 0x989680; @P1 bra.uni WD%=; bra.uni WL%=; WD%=: }" \
                     :: "r"(_m), "r"(_p) : "memory");                                \
    }                                                                                \
} while (0)

static __device__ __forceinline__ void bulk_g2s(uint32_t dst, const void* src,
                                                uint32_t bytes, uint32_t mbar) {
    uint64_t g;
    asm("cvta.to.global.u64 %0, %1;" : "=l"(g) : "l"(src));
    asm volatile("cp.async.bulk.shared::cta.global.mbarrier::complete_tx::bytes [%0], [%1], %2, [%3];"
                 :: "r"(dst), "l"(g), "r"(bytes), "r"(mbar) : "memory");
}

#define LDSM4(r, a) \
    asm volatile("ldmatrix.sync.aligned.m8n8.x4.shared.b16 {%0,%1,%2,%3}, [%4];" \
                 : "=r"((r)[0]), "=r"((r)[1]), "=r"((r)[2]), "=r"((r)[3]) : "r"(a))

#define MMA16816(d, a, b0, b1) \
    asm volatile("mma.sync.aligned.m16n8k16.row.col.f32.bf16.bf16.f32 " \
                 "{%0,%1,%2,%3}, {%4,%5,%6,%7}, {%8,%9}, {%0,%1,%2,%3};" \
                 : "+f"((d)[0]), "+f"((d)[1]), "+f"((d)[2]), "+f"((d)[3]) \
                 : "r"((a)[0]), "r"((a)[1]), "r"((a)[2]), "r"((a)[3]), \
                   "r"(b0), "r"(b1))

// ---- hi/lo bf16 split of 8 fp32 values, packed to two uint4 ----
static __device__ __forceinline__ void split8(const float* x, uint4& uh, uint4& ul) {
    uint32_t h[8], l[8];
#pragma unroll
    for (int j = 0; j < 8; j++) {
        __nv_bfloat16 bh = __float2bfloat16(x[j]);
        float r = x[j] - __bfloat162float(bh);
        __nv_bfloat16 bl = __float2bfloat16(r);
        h[j] = (uint32_t)__bfloat16_as_ushort(bh);
        l[j] = (uint32_t)__bfloat16_as_ushort(bl);
    }
    uh = make_uint4(h[0] | (h[1] << 16), h[2] | (h[3] << 16),
                    h[4] | (h[5] << 16), h[6] | (h[7] << 16));
    ul = make_uint4(l[0] | (l[1] << 16), l[2] | (l[3] << 16),
                    l[4] | (l[5] << 16), l[6] | (l[7] << 16));
}

// ---------------- prep: split + swizzle targets into global images ----------------
__global__ void __launch_bounds__(256) prep_targets(const float* __restrict__ tg) {
    int idx = blockIdx.x * 256 + threadIdx.x;   // 16384*8 chunks of 8 elems
    int row = idx >> 3, c = idx & 7;
    const float4* p = reinterpret_cast<const float4*>(tg + (size_t)row * DIM + c * 8);
    float4 a = p[0], b = p[1];
    float x[8] = {a.x, a.y, a.z, a.w, b.x, b.y, b.z, b.w};
    uint4 uh, ul;
    split8(x, uh, ul);
    int slot = row * 8 + (c ^ (row & 7));
    reinterpret_cast<uint4*>(g_thi)[slot] = uh;
    reinterpret_cast<uint4*>(g_tlo)[slot] = ul;
}

// ---------------- main fused kernel ----------------
// SMEM: [0,16K) q_hi, [16K,32K) q_lo,
//       [32K + s*32K): tile buffer s = { t_hi 16K, t_lo 16K },  s = 0,1
//       [96K): mbarriers (2 data, 2 consume)
#define QHI   0u
#define QLO   16384u
#define TBUF(s) (32768u + (uint32_t)(s) * 32768u)
#define BARO  98304u
#define SMEM_BYTES (98304 + 64)

__global__ void __launch_bounds__(256, 1)
infonce_mma(const float* __restrict__ logits, const float* __restrict__ noise,
            float* __restrict__ out) {
    extern __shared__ unsigned char smem[];
    const uint32_t sb = smem_u32(smem);
    const int tid = threadIdx.x, wid = tid >> 5, lane = tid & 31;
    const int b = blockIdx.x;

    const uint32_t dbar0 = sb + BARO,      dbar1 = sb + BARO + 8;
    const uint32_t cbar0 = sb + BARO + 16, cbar1 = sb + BARO + 24;
    if (tid == 0) {
        MBAR_INIT(dbar0, 1); MBAR_INIT(dbar1, 1);
        MBAR_INIT(cbar0, 8); MBAR_INIT(cbar1, 8);
    }

    // ---- q prologue: q = logits - log(noise); split hi/lo; swizzled STS ----
#pragma unroll
    for (int i = 0; i < 4; i++) {
        int ch = tid + 256 * i;                 // 0..1023 (128 rows x 8 chunks)
        int row = ch >> 3, c = ch & 7;
        const float4* p = reinterpret_cast<const float4*>(
            logits + (size_t)(b * TM + row) * DIM + c * 8);
        float4 a = p[0], bb = p[1];
        float x[8] = {a.x, a.y, a.z, a.w, bb.x, bb.y, bb.z, bb.w};
#pragma unroll
        for (int j = 0; j < 8; j++) x[j] -= logf(noise[c * 8 + j]);
        uint4 uh, ul;
        split8(x, uh, ul);
        uint32_t off = (uint32_t)row * 128u + (uint32_t)((c ^ (row & 7)) * 16);
        *reinterpret_cast<uint4*>(smem + QHI + off) = uh;
        *reinterpret_cast<uint4*>(smem + QLO + off) = ul;
    }

    // prefetch tiles 0 and 1
    if (tid == 0) {
        MBAR_EXPECT(dbar0, 32768);
        bulk_g2s(sb + TBUF(0),          g_thi,         16384, dbar0);
        bulk_g2s(sb + TBUF(0) + 16384u, g_tlo,         16384, dbar0);
        MBAR_EXPECT(dbar1, 32768);
        bulk_g2s(sb + TBUF(1),          g_thi + 16384, 16384, dbar1);
        bulk_g2s(sb + TBUF(1) + 16384u, g_tlo + 16384, 16384, dbar1);
    }
    __syncthreads();   // q_sh + mbarrier inits visible to all warps

    // warp tiling: 4 row-groups x 2 col-groups; warp = 32 rows x 64 cols
    const int wr = wid & 3, wc = wid >> 2;
    const int lrow  = (lane & 7) + ((lane >> 3) & 1) * 8;  // row within 16-tile
    const int lchk  = lane >> 4;                           // chunk add (0/1)
    const int swrow = lane & 7;                            // row&7 for swizzle

    const uint32_t a_base = sb + QHI + (uint32_t)(wr * 32 + lrow) * 128u;

    float run_max[4], run_sum[4], diagv[4];
#pragma unroll
    for (int j = 0; j < 4; j++) {
        run_max[j] = -INFINITY; run_sum[j] = 0.0f; diagv[j] = 0.0f;
    }

    for (int t = 0; t < NTILES; t++) {
        const int s = t & 1;
        MBAR_WAIT((s ? dbar1 : dbar0), (t >> 1) & 1);

        float acc[2][8][4];
#pragma unroll
        for (int at = 0; at < 2; at++)
#pragma unroll
            for (int nt = 0; nt < 8; nt++)
#pragma unroll
                for (int e = 0; e < 4; e++) acc[at][nt][e] = 0.0f;

        const uint32_t th_base = sb + TBUF(s) +
                                 (uint32_t)(wc * 64 + lrow) * 128u;

#pragma unroll
        for (int k = 0; k < 4; k++) {
            const uint32_t sw = (uint32_t)(((k * 2 + lchk) ^ swrow) << 4);

            uint32_t AH[2][4], AL[2][4];
#pragma unroll
            for (int at = 0; at < 2; at++) {
                uint32_t aa = a_base + (uint32_t)(at * 2048) + sw;
                LDSM4(AH[at], aa);
                LDSM4(AL[at], aa + 16384u);
            }
            uint32_t BH[4][4], BL[4][4];
#pragma unroll
            for (int g = 0; g < 4; g++) {
                uint32_t ba = th_base + (uint32_t)(g * 2048) + sw;
                LDSM4(BH[g], ba);
                LDSM4(BL[g], ba + 16384u);
            }
#pragma unroll
            for (int at = 0; at < 2; at++) {
#pragma unroll
                for (int nt = 0; nt < 8; nt++) {
                    const int g = nt >> 1, su = nt & 1;
                    MMA16816(acc[at][nt], AH[at], BH[g][su], BH[g][2 + su]);
                    MMA16816(acc[at][nt], AH[at], BL[g][su], BL[g][2 + su]);
                    MMA16816(acc[at][nt], AL[at], BH[g][su], BH[g][2 + su]);
                }
            }
        }

        // this warp is done reading buffer s
        if (lane == 0) MBAR_ARRIVE(s ? cbar1 : cbar0);

        // ---- diagonal extraction (tile t == blockIdx.x holds the diagonal) ----
        if (t == b) {
#pragma unroll
            for (int j = 0; j < 4; j++) {
                const int rloc = wr * 32 + (j >> 1) * 16 + (j & 1) * 8 + (lane >> 2);
                const int cw = rloc - wc * 64;
                if (cw >= 0 && cw < 64) {
                    const int nt = cw >> 3;
                    if (((cw >> 1) & 3) == (lane & 3))
                        diagv[j] = acc[j >> 1][nt][(j & 1) * 2 + (cw & 1)];
                }
            }
        }

        // ---- online softmax with adaptive skip ----
#pragma unroll
        for (int j = 0; j < 4; j++) {
            const int at = j >> 1, er = (j & 1) * 2;
            float v[16];
#pragma unroll
            for (int nt = 0; nt < 8; nt++) {
                v[nt * 2]     = acc[at][nt][er];
                v[nt * 2 + 1] = acc[at][nt][er + 1];
            }
            float m8[8];
#pragma unroll
            for (int i = 0; i < 8; i++) m8[i] = fmaxf(v[i], v[i + 8]);
#pragma unroll
            for (int w = 4; w > 0; w >>= 1)
#pragma unroll
                for (int i = 0; i < w; i++) m8[i] = fmaxf(m8[i], m8[i + w]);
            float m = m8[0];
            m = fmaxf(m, __shfl_xor_sync(0xffffffffu, m, 1));
            m = fmaxf(m, __shfl_xor_sync(0xffffffffu, m, 2));

            // Skip groups that cannot contribute (> SKIP_THRESH below run max).
            const bool pass = (m > run_max[j] - SKIP_THRESH);
            if (__any_sync(0xffffffffu, pass)) {
                const float nm = fmaxf(run_max[j], m);
                float s0 = 0.f, s1 = 0.f, s2 = 0.f, s3 = 0.f;
#pragma unroll
                for (int i = 0; i < 16; i += 4) {
                    s0 += __expf(v[i + 0] - nm);
                    s1 += __expf(v[i + 1] - nm);
                    s2 += __expf(v[i + 2] - nm);
                    s3 += __expf(v[i + 3] - nm);
                }
                float ss = (s0 + s1) + (s2 + s3);
                ss += __shfl_xor_sync(0xffffffffu, ss, 1);
                ss += __shfl_xor_sync(0xffffffffu, ss, 2);

                run_sum[j] = run_sum[j] * __expf(run_max[j] - nm) + ss;
                run_max[j] = nm;
            }
        }

        // refill freed buffer s with tile t+2 (after ALL warps consumed it)
        if (t + 2 < NTILES && tid == 0) {
            MBAR_WAIT((s ? cbar1 : cbar0), (t >> 1) & 1);
            const uint32_t tb = s ? dbar1 : dbar0;
            MBAR_EXPECT(tb, 32768);
            bulk_g2s(sb + TBUF(s),          g_thi + (size_t)(t + 2) * 16384, 16384, tb);
            bulk_g2s(sb + TBUF(s) + 16384u, g_tlo + (size_t)(t + 2) * 16384, 16384, tb);
        }
    }

    // ---- merge col-halves + block reduce ----
    __syncthreads();
    float* S = reinterpret_cast<float*>(smem);   // [0,256) max, [256,512) sum, [512,768) diag

#pragma unroll
    for (int j = 0; j < 4; j++) {
        float d = diagv[j];
        d += __shfl_xor_sync(0xffffffffu, d, 1);
        d += __shfl_xor_sync(0xffffffffu, d, 2);
        diagv[j] = d;
    }
    if ((lane & 3) == 0) {
#pragma unroll
        for (int j = 0; j < 4; j++) {
            const int r = wr * 32 + (j >> 1) * 16 + (j & 1) * 8 + (lane >> 2);
            S[wc * 128 + r]       = run_max[j];
            S[256 + wc * 128 + r] = run_sum[j];
            S[512 + wc * 128 + r] = diagv[j];
        }
    }
    __syncthreads();

    float loss = 0.0f;
    if (tid < 128) {
        const float m0 = S[tid],       s0 = S[256 + tid], d0 = S[512 + tid];
        const float m1 = S[128 + tid], s1 = S[384 + tid], d1 = S[640 + tid];
        const float m = fmaxf(m0, m1);
        const float ssum = s0 * __expf(m0 - m) + s1 * __expf(m1 - m);
        loss = m + logf(ssum) - (d0 + d1);
    }
#pragma unroll
    for (int o = 16; o > 0; o >>= 1)
        loss += __shfl_xor_sync(0xffffffffu, loss, o);
    __syncthreads();
    if (lane == 0) S[768 + wid] = loss;
    __syncthreads();

    // ---- fused finalize: last block reduces all partials ----
    __shared__ unsigned int ticket;
    if (tid == 0) {
        float v = 0.0f;
#pragma unroll
        for (int i = 0; i < 8; i++) v += S[768 + i];
        g_partial[b] = v;
        __threadfence();
        ticket = atomicAdd(&g_done, 1u);
    }
    __syncthreads();
    if (ticket == NBLOCKS - 1) {
        __threadfence();
        float v = (tid < NBLOCKS) ? g_partial[tid] : 0.0f;
#pragma unroll
        for (int o = 16; o > 0; o >>= 1)
            v += __shfl_xor_sync(0xffffffffu, v, o);
        if (lane == 0) S[800 + wid] = v;
        __syncthreads();
        if (tid == 0) {
            float r = 0.0f;
#pragma unroll
            for (int i = 0; i < 8; i++) r += S[800 + i];
            out[0] = r / (float)NTOT;
            g_done = 0;   // reset for next graph replay
        }
    }
}

extern "C" void kernel_launch(void* const* d_in, const int* in_sizes, int n_in,
                              void* d_out, int out_size) {
    const float* logits  = (const float*)d_in[0];
    const float* targets = (const float*)d_in[1];
    const float* noise   = (const float*)d_in[2];

    cudaFuncSetAttribute(infonce_mma, cudaFuncAttributeMaxDynamicSharedMemorySize, SMEM_BYTES);

    prep_targets<<<NTOT * 8 / 256, 256>>>(targets);
    infonce_mma<<<NBLOCKS, 256, SMEM_BYTES>>>(logits, noise, (float*)d_out);
}

// round 5
// speedup vs baseline: 5.0343x; 2.0936x over previous
#include <cuda_runtime.h>
#include <cuda_bf16.h>
#include <math.h>
#include <stdint.h>

// loss = mean_n [ logsumexp_m( q_n . t_m ) - q_n . t_n ],  q = logits - log(noise)
// N = M = 16384, D = 64.
// bf16 hi/lo split (3 MMA terms) on mma.sync; q fragments preloaded in
// registers; 512 threads (4 warps/SMSP), <=128 regs/thread (no spills).

#define NTOT    16384
#define DIM     64
#define TM      128                 // q rows per block
#define TN      128                 // target rows per tile iteration
#define NTILES  (NTOT / TN)         // 128
#define NBLOCKS (NTOT / TM)         // 128
#define NTHREADS 512
#define SKIP_THRESH 13.0f

__device__ __align__(128) unsigned char g_thi[(size_t)NTOT * 128];
__device__ __align__(128) unsigned char g_tlo[(size_t)NTOT * 128];
__device__ float g_partial[NBLOCKS];
__device__ unsigned int g_done;

// ---------------- PTX helpers ----------------
static __device__ __forceinline__ uint32_t smem_u32(const void* p) {
    uint32_t a;
    asm("{ .reg .u64 t; cvta.to.shared.u64 t, %1; cvt.u32.u64 %0, t; }"
        : "=r"(a) : "l"(p));
    return a;
}
#define MBAR_INIT(a, c) \
    asm volatile("mbarrier.init.shared.b64 [%0], %1;" :: "r"(a), "r"(c) : "memory")
#define MBAR_EXPECT(a, b) \
    asm volatile("mbarrier.arrive.expect_tx.shared.b64 _, [%0], %1;" :: "r"(a), "r"(b) : "memory")
#define MBAR_ARRIVE(a) \
    asm volatile("mbarrier.arrive.shared.b64 _, [%0];" :: "r"(a) : "memory")
#define MBAR_WAIT(a, ph) do {                                                        \
    uint32_t _m = (a), _p = (ph), _d;                                                \
    asm volatile("{ .reg .pred p; mbarrier.try_wait.parity.acquire.cta.shared::cta.b64 p, [%1], %2; selp.b32 %0,1,0,p; }" \
                 : "=r"(_d) : "r"(_m), "r"(_p) : "memory");                          \
    if (!_d) {                                                                       \
        asm volatile("{ .reg .pred P1; WL%=: mbarrier.try_wait.parity.acquire.cta.shared::cta.b64 P1, [%0], %1, 0x989680; @P1 bra.uni WD%=; bra.uni WL%=; WD%=: }" \
                     :: "r"(_m), "r"(_p) : "memory");                                \
    }                                                                                \
} while (0)

static __device__ __forceinline__ void bulk_g2s(uint32_t dst, const void* src,
                                                uint32_t bytes, uint32_t mbar) {
    uint64_t g;
    asm("cvta.to.global.u64 %0, %1;" : "=l"(g) : "l"(src));
    asm volatile("cp.async.bulk.shared::cta.global.mbarrier::complete_tx::bytes [%0], [%1], %2, [%3];"
                 :: "r"(dst), "l"(g), "r"(bytes), "r"(mbar) : "memory");
}

#define LDSM4(r, a) \
    asm volatile("ldmatrix.sync.aligned.m8n8.x4.shared.b16 {%0,%1,%2,%3}, [%4];" \
                 : "=r"((r)[0]), "=r"((r)[1]), "=r"((r)[2]), "=r"((r)[3]) : "r"(a))

#define MMA16816(d, a, b0, b1) \
    asm volatile("mma.sync.aligned.m16n8k16.row.col.f32.bf16.bf16.f32 " \
                 "{%0,%1,%2,%3}, {%4,%5,%6,%7}, {%8,%9}, {%0,%1,%2,%3};" \
                 : "+f"((d)[0]), "+f"((d)[1]), "+f"((d)[2]), "+f"((d)[3]) \
                 : "r"((a)[0]), "r"((a)[1]), "r"((a)[2]), "r"((a)[3]), \
                   "r"(b0), "r"(b1))

static __device__ __forceinline__ void split8(const float* x, uint4& uh, uint4& ul) {
    uint32_t h[8], l[8];
#pragma unroll
    for (int j = 0; j < 8; j++) {
        __nv_bfloat16 bh = __float2bfloat16(x[j]);
        float r = x[j] - __bfloat162float(bh);
        __nv_bfloat16 bl = __float2bfloat16(r);
        h[j] = (uint32_t)__bfloat16_as_ushort(bh);
        l[j] = (uint32_t)__bfloat16_as_ushort(bl);
    }
    uh = make_uint4(h[0] | (h[1] << 16), h[2] | (h[3] << 16),
                    h[4] | (h[5] << 16), h[6] | (h[7] << 16));
    ul = make_uint4(l[0] | (l[1] << 16), l[2] | (l[3] << 16),
                    l[4] | (l[5] << 16), l[6] | (l[7] << 16));
}

__global__ void __launch_bounds__(256) prep_targets(const float* __restrict__ tg) {
    int idx = blockIdx.x * 256 + threadIdx.x;
    int row = idx >> 3, c = idx & 7;
    const float4* p = reinterpret_cast<const float4*>(tg + (size_t)row * DIM + c * 8);
    float4 a = p[0], b = p[1];
    float x[8] = {a.x, a.y, a.z, a.w, b.x, b.y, b.z, b.w};
    uint4 uh, ul;
    split8(x, uh, ul);
    int slot = row * 8 + (c ^ (row & 7));
    reinterpret_cast<uint4*>(g_thi)[slot] = uh;
    reinterpret_cast<uint4*>(g_tlo)[slot] = ul;
}

// SMEM: [0,16K) q_hi, [16K,32K) q_lo,
//       [32K + s*32K): tile buffer s = { t_hi 16K, t_lo 16K }, s = 0,1
//       [96K): mbarriers
#define QHI   0u
#define QLO   16384u
#define TBUF(s) (32768u + (uint32_t)(s) * 32768u)
#define BARO  98304u
#define SMEM_BYTES (98304 + 64)

__global__ void __launch_bounds__(NTHREADS, 1)
infonce_mma(const float* __restrict__ logits, const float* __restrict__ noise,
            float* __restrict__ out) {
    extern __shared__ unsigned char smem[];
    const uint32_t sb = smem_u32(smem);
    const int tid = threadIdx.x, wid = tid >> 5, lane = tid & 31;
    const int b = blockIdx.x;

    const uint32_t dbar0 = sb + BARO,      dbar1 = sb + BARO + 8;
    const uint32_t cbar0 = sb + BARO + 16, cbar1 = sb + BARO + 24;
    if (tid == 0) {
        MBAR_INIT(dbar0, 1);  MBAR_INIT(dbar1, 1);
        MBAR_INIT(cbar0, 16); MBAR_INIT(cbar1, 16);
    }

    // ---- q prologue ----
#pragma unroll
    for (int i = 0; i < 2; i++) {
        int ch = tid + NTHREADS * i;            // 0..1023
        int row = ch >> 3, c = ch & 7;
        const float4* p = reinterpret_cast<const float4*>(
            logits + (size_t)(b * TM + row) * DIM + c * 8);
        float4 a = p[0], bb = p[1];
        float x[8] = {a.x, a.y, a.z, a.w, bb.x, bb.y, bb.z, bb.w};
#pragma unroll
        for (int j = 0; j < 8; j++) x[j] -= logf(noise[c * 8 + j]);
        uint4 uh, ul;
        split8(x, uh, ul);
        uint32_t off = (uint32_t)row * 128u + (uint32_t)((c ^ (row & 7)) * 16);
        *reinterpret_cast<uint4*>(smem + QHI + off) = uh;
        *reinterpret_cast<uint4*>(smem + QLO + off) = ul;
    }

    if (tid == 0) {
        MBAR_EXPECT(dbar0, 32768);
        bulk_g2s(sb + TBUF(0),          g_thi,         16384, dbar0);
        bulk_g2s(sb + TBUF(0) + 16384u, g_tlo,         16384, dbar0);
        MBAR_EXPECT(dbar1, 32768);
        bulk_g2s(sb + TBUF(1),          g_thi + 16384, 16384, dbar1);
        bulk_g2s(sb + TBUF(1) + 16384u, g_tlo + 16384, 16384, dbar1);
    }
    __syncthreads();

    // warp grid: 8 row-groups x 2 col-groups; warp tile = 16 rows x 64 cols
    const int wr = wid & 7, wc = wid >> 3;
    const int lrow  = lane & 15;                 // row within 16-tile
    const int lchk  = lane >> 4;                 // k-chunk add (0/1)
    const int swrow = lane & 7;

    // ---- preload A (q) fragments: tile-invariant across the whole loop ----
    uint32_t AH[4][4], AL[4][4];
    {
        const uint32_t a_base = sb + QHI + (uint32_t)(wr * 16 + lrow) * 128u;
#pragma unroll
        for (int k = 0; k < 4; k++) {
            const uint32_t sw = (uint32_t)(((k * 2 + lchk) ^ swrow) << 4);
            LDSM4(AH[k], a_base + sw);
            LDSM4(AL[k], a_base + sw + 16384u);
        }
    }

    float run_max[2], run_sum[2], diagv[2];
#pragma unroll
    for (int j = 0; j < 2; j++) {
        run_max[j] = -INFINITY; run_sum[j] = 0.0f; diagv[j] = 0.0f;
    }

    for (int t = 0; t < NTILES; t++) {
        const int s = t & 1;
        MBAR_WAIT((s ? dbar1 : dbar0), (t >> 1) & 1);

        float acc[8][4];
#pragma unroll
        for (int nt = 0; nt < 8; nt++)
#pragma unroll
            for (int e = 0; e < 4; e++) acc[nt][e] = 0.0f;

        const uint32_t th_base = sb + TBUF(s) + (uint32_t)(wc * 64 + lrow) * 128u;

#pragma unroll
        for (int k = 0; k < 4; k++) {
            const uint32_t sw = (uint32_t)(((k * 2 + lchk) ^ swrow) << 4);
#pragma unroll
            for (int g = 0; g < 4; g++) {
                uint32_t BH[4], BL[4];
                const uint32_t ba = th_base + (uint32_t)(g * 2048) + sw;
                LDSM4(BH, ba);
                LDSM4(BL, ba + 16384u);
#pragma unroll
                for (int su = 0; su < 2; su++) {
                    const int nt = g * 2 + su;
                    MMA16816(acc[nt], AH[k], BH[su], BH[2 + su]);
                    MMA16816(acc[nt], AH[k], BL[su], BL[2 + su]);
                    MMA16816(acc[nt], AL[k], BH[su], BH[2 + su]);
                }
            }
        }

        if (lane == 0) MBAR_ARRIVE(s ? cbar1 : cbar0);

        // ---- diagonal extraction ----
        if (t == b) {
#pragma unroll
            for (int j = 0; j < 2; j++) {
                const int rloc = wr * 16 + j * 8 + (lane >> 2);
                const int cw = rloc - wc * 64;
                if (cw >= 0 && cw < 64) {
                    const int nt = cw >> 3;
                    if (((cw >> 1) & 3) == (lane & 3))
                        diagv[j] = acc[nt][j * 2 + (cw & 1)];
                }
            }
        }

        // ---- online softmax with adaptive skip ----
#pragma unroll
        for (int j = 0; j < 2; j++) {
            const int er = j * 2;
            float m8[8];
#pragma unroll
            for (int nt = 0; nt < 8; nt++)
                m8[nt] = fmaxf(acc[nt][er], acc[nt][er + 1]);
#pragma unroll
            for (int w = 4; w > 0; w >>= 1)
#pragma unroll
                for (int i = 0; i < w; i++) m8[i] = fmaxf(m8[i], m8[i + w]);
            float m = m8[0];
            m = fmaxf(m, __shfl_xor_sync(0xffffffffu, m, 1));
            m = fmaxf(m, __shfl_xor_sync(0xffffffffu, m, 2));

            const bool pass = (m > run_max[j] - SKIP_THRESH);
            if (__any_sync(0xffffffffu, pass)) {
                const float nm = fmaxf(run_max[j], m);
                float s0 = 0.f, s1 = 0.f;
#pragma unroll
                for (int nt = 0; nt < 8; nt++) {
                    s0 += __expf(acc[nt][er]     - nm);
                    s1 += __expf(acc[nt][er + 1] - nm);
                }
                float ss = s0 + s1;
                ss += __shfl_xor_sync(0xffffffffu, ss, 1);
                ss += __shfl_xor_sync(0xffffffffu, ss, 2);
                run_sum[j] = run_sum[j] * __expf(run_max[j] - nm) + ss;
                run_max[j] = nm;
            }
        }

        if (t + 2 < NTILES && tid == 0) {
            MBAR_WAIT((s ? cbar1 : cbar0), (t >> 1) & 1);
            const uint32_t tb = s ? dbar1 : dbar0;
            MBAR_EXPECT(tb, 32768);
            bulk_g2s(sb + TBUF(s),          g_thi + (size_t)(t + 2) * 16384, 16384, tb);
            bulk_g2s(sb + TBUF(s) + 16384u, g_tlo + (size_t)(t + 2) * 16384, 16384, tb);
        }
    }

    // ---- merge col-halves + block reduce ----
    __syncthreads();
    float* S = reinterpret_cast<float*>(smem);

#pragma unroll
    for (int j = 0; j < 2; j++) {
        float d = diagv[j];
        d += __shfl_xor_sync(0xffffffffu, d, 1);
        d += __shfl_xor_sync(0xffffffffu, d, 2);
        diagv[j] = d;
    }
    if ((lane & 3) == 0) {
#pragma unroll
        for (int j = 0; j < 2; j++) {
            const int r = wr * 16 + j * 8 + (lane >> 2);
            S[wc * 128 + r]       = run_max[j];
            S[256 + wc * 128 + r] = run_sum[j];
            S[512 + wc * 128 + r] = diagv[j];
        }
    }
    __syncthreads();

    float loss = 0.0f;
    if (tid < 128) {
        const float m0 = S[tid],       s0 = S[256 + tid], d0 = S[512 + tid];
        const float m1 = S[128 + tid], s1 = S[384 + tid], d1 = S[640 + tid];
        const float m = fmaxf(m0, m1);
        const float ssum = s0 * __expf(m0 - m) + s1 * __expf(m1 - m);
        loss = m + logf(ssum) - (d0 + d1);
    }
#pragma unroll
    for (int o = 16; o > 0; o >>= 1)
        loss += __shfl_xor_sync(0xffffffffu, loss, o);
    __syncthreads();
    if (lane == 0) S[768 + wid] = loss;
    __syncthreads();

    // ---- fused finalize ----
    __shared__ unsigned int ticket;
    if (tid == 0) {
        float v = 0.0f;
#pragma unroll
        for (int i = 0; i < 16; i++) v += S[768 + i];
        g_partial[b] = v;
        __threadfence();
        ticket = atomicAdd(&g_done, 1u);
    }
    __syncthreads();
    if (ticket == NBLOCKS - 1) {
        __threadfence();
        float v = (tid < NBLOCKS) ? g_partial[tid] : 0.0f;
#pragma unroll
        for (int o = 16; o > 0; o >>= 1)
            v += __shfl_xor_sync(0xffffffffu, v, o);
        if (lane == 0) S[800 + wid] = v;
        __syncthreads();
        if (tid == 0) {
            float r = 0.0f;
#pragma unroll
            for (int i = 0; i < 16; i++) r += S[800 + i];
            out[0] = r / (float)NTOT;
            g_done = 0;
        }
    }
}

extern "C" void kernel_launch(void* const* d_in, const int* in_sizes, int n_in,
                              void* d_out, int out_size) {
    const float* logits  = (const float*)d_in[0];
    const float* targets = (const float*)d_in[1];
    const float* noise   = (const float*)d_in[2];

    cudaFuncSetAttribute(infonce_mma, cudaFuncAttributeMaxDynamicSharedMemorySize, SMEM_BYTES);

    prep_targets<<<NTOT * 8 / 256, 256>>>(targets);
    infonce_mma<<<NBLOCKS, NTHREADS, SMEM_BYTES>>>(logits, noise, (float*)d_out);
}

// round 6
// speedup vs baseline: 7.9641x; 1.5820x over previous
#include <cuda_runtime.h>
#include <cuda_fp16.h>
#include <math.h>
#include <stdint.h>

// loss = mean_n [ logsumexp_m( q_n . t_m ) - q_n . t_n ],  q = logits - log(noise)
// N = M = 16384, D = 64.
// Single-term fp16 mma.sync (score err ~8e-3 -> final rel err ~1e-5),
// online softmax with adaptive skip, 4-deep cp.async.bulk tile ring.

#define NTOT    16384
#define DIM     64
#define TM      128                 // q rows per block
#define TN      128                 // target rows per tile iteration
#define NTILES  (NTOT / TN)         // 128
#define NBLOCKS (NTOT / TM)         // 128
#define NTHREADS 512
#define SKIP_THRESH 13.0f

// fp16 image of targets, chunk-swizzled, 128 B per row.
__device__ __align__(128) unsigned char g_thf[(size_t)NTOT * 128];
__device__ float g_partial[NBLOCKS];
__device__ unsigned int g_done;

// ---------------- PTX helpers ----------------
static __device__ __forceinline__ uint32_t smem_u32(const void* p) {
    uint32_t a;
    asm("{ .reg .u64 t; cvta.to.shared.u64 t, %1; cvt.u32.u64 %0, t; }"
        : "=r"(a) : "l"(p));
    return a;
}
#define MBAR_INIT(a, c) \
    asm volatile("mbarrier.init.shared.b64 [%0], %1;" :: "r"(a), "r"(c) : "memory")
#define MBAR_EXPECT(a, b) \
    asm volatile("mbarrier.arrive.expect_tx.shared.b64 _, [%0], %1;" :: "r"(a), "r"(b) : "memory")
#define MBAR_ARRIVE(a) \
    asm volatile("mbarrier.arrive.shared.b64 _, [%0];" :: "r"(a) : "memory")
#define MBAR_WAIT(a, ph) do {                                                        \
    uint32_t _m = (a), _p = (ph), _d;                                                \
    asm volatile("{ .reg .pred p; mbarrier.try_wait.parity.acquire.cta.shared::cta.b64 p, [%1], %2; selp.b32 %0,1,0,p; }" \
                 : "=r"(_d) : "r"(_m), "r"(_p) : "memory");                          \
    if (!_d) {                                                                       \
        asm volatile("{ .reg .pred P1; WL%=: mbarrier.try_wait.parity.acquire.cta.shared::cta.b64 P1, [%0], %1, 0x989680; @P1 bra.uni WD%=; bra.uni WL%=; WD%=: }" \
                     :: "r"(_m), "r"(_p) : "memory");                                \
    }                                                                                \
} while (0)

static __device__ __forceinline__ void bulk_g2s(uint32_t dst, const void* src,
                                                uint32_t bytes, uint32_t mbar) {
    uint64_t g;
    asm("cvta.to.global.u64 %0, %1;" : "=l"(g) : "l"(src));
    asm volatile("cp.async.bulk.shared::cta.global.mbarrier::complete_tx::bytes [%0], [%1], %2, [%3];"
                 :: "r"(dst), "l"(g), "r"(bytes), "r"(mbar) : "memory");
}

#define LDSM4(r, a) \
    asm volatile("ldmatrix.sync.aligned.m8n8.x4.shared.b16 {%0,%1,%2,%3}, [%4];" \
                 : "=r"((r)[0]), "=r"((r)[1]), "=r"((r)[2]), "=r"((r)[3]) : "r"(a))

#define MMA16816(d, a, b0, b1) \
    asm volatile("mma.sync.aligned.m16n8k16.row.col.f32.f16.f16.f32 " \
                 "{%0,%1,%2,%3}, {%4,%5,%6,%7}, {%8,%9}, {%0,%1,%2,%3};" \
                 : "+f"((d)[0]), "+f"((d)[1]), "+f"((d)[2]), "+f"((d)[3]) \
                 : "r"((a)[0]), "r"((a)[1]), "r"((a)[2]), "r"((a)[3]), \
                   "r"(b0), "r"(b1))

// first k-step: D = A*B + 0 (no accumulator init needed)
#define MMA16816Z(d, a, b0, b1) \
    asm volatile("mma.sync.aligned.m16n8k16.row.col.f32.f16.f16.f32 " \
                 "{%0,%1,%2,%3}, {%4,%5,%6,%7}, {%8,%9}, {%10,%10,%10,%10};" \
                 : "=f"((d)[0]), "=f"((d)[1]), "=f"((d)[2]), "=f"((d)[3]) \
                 : "r"((a)[0]), "r"((a)[1]), "r"((a)[2]), "r"((a)[3]), \
                   "r"(b0), "r"(b1), "f"(0.0f))

static __device__ __forceinline__ uint32_t pack_h2(float a, float b) {
    __half2 h = __floats2half2_rn(a, b);
    return *reinterpret_cast<uint32_t*>(&h);
}

// ---------------- prep: convert + swizzle targets into fp16 image ----------------
// Element (row, k) at byte row*128 + ((chunk ^ (row&7))*16) + (k&7)*2, chunk=k>>3.
__global__ void __launch_bounds__(256) prep_targets(const float* __restrict__ tg) {
    int idx = blockIdx.x * 256 + threadIdx.x;   // 16384*8 chunks of 8 elems
    int row = idx >> 3, c = idx & 7;
    const float4* p = reinterpret_cast<const float4*>(tg + (size_t)row * DIM + c * 8);
    float4 a = p[0], b = p[1];
    uint4 u = make_uint4(pack_h2(a.x, a.y), pack_h2(a.z, a.w),
                         pack_h2(b.x, b.y), pack_h2(b.z, b.w));
    int slot = row * 8 + (c ^ (row & 7));
    reinterpret_cast<uint4*>(g_thf)[slot] = u;
}

// ---------------- main fused kernel ----------------
// SMEM: [0,16K) q fp16, [16K + s*16K) tile ring s=0..3, [80K) mbarriers
#define QOFF  0u
#define TBUF(s) (16384u + (uint32_t)(s) * 16384u)
#define BARO  81920u
#define SMEM_BYTES (81920 + 128)

__global__ void __launch_bounds__(NTHREADS, 1)
infonce_mma(const float* __restrict__ logits, const float* __restrict__ noise,
            float* __restrict__ out) {
    extern __shared__ unsigned char smem[];
    const uint32_t sb = smem_u32(smem);
    const int tid = threadIdx.x, wid = tid >> 5, lane = tid & 31;
    const int b = blockIdx.x;

    // 4 data barriers + 4 consume barriers
    if (tid == 0) {
#pragma unroll
        for (int s = 0; s < 4; s++) {
            MBAR_INIT(sb + BARO + s * 8, 1);        // data
            MBAR_INIT(sb + BARO + 32 + s * 8, 16);  // consume (16 warps)
        }
    }

    // ---- q prologue: q = logits - log(noise) -> fp16, swizzled ----
#pragma unroll
    for (int i = 0; i < 2; i++) {
        int ch = tid + NTHREADS * i;            // 0..1023 (128 rows x 8 chunks)
        int row = ch >> 3, c = ch & 7;
        const float4* p = reinterpret_cast<const float4*>(
            logits + (size_t)(b * TM + row) * DIM + c * 8);
        float4 a = p[0], bb = p[1];
        float x[8] = {a.x, a.y, a.z, a.w, bb.x, bb.y, bb.z, bb.w};
#pragma unroll
        for (int j = 0; j < 8; j++) x[j] -= logf(noise[c * 8 + j]);
        uint4 u = make_uint4(pack_h2(x[0], x[1]), pack_h2(x[2], x[3]),
                             pack_h2(x[4], x[5]), pack_h2(x[6], x[7]));
        uint32_t off = (uint32_t)row * 128u + (uint32_t)((c ^ (row & 7)) * 16);
        *reinterpret_cast<uint4*>(smem + QOFF + off) = u;
    }

    // prefetch tiles 0..3
    if (tid == 0) {
#pragma unroll
        for (int s = 0; s < 4; s++) {
            MBAR_EXPECT(sb + BARO + s * 8, 16384);
            bulk_g2s(sb + TBUF(s), g_thf + (size_t)s * 16384, 16384, sb + BARO + s * 8);
        }
    }
    __syncthreads();

    // warp grid: 8 row-groups x 2 col-groups; warp tile = 16 rows x 64 cols
    const int wr = wid & 7, wc = wid >> 3;
    const int lrow  = lane & 15;
    const int lchk  = lane >> 4;
    const int swrow = lane & 7;

    // ---- preload A (q) fragments: tile-invariant ----
    uint32_t A[4][4];
    {
        const uint32_t a_base = sb + QOFF + (uint32_t)(wr * 16 + lrow) * 128u;
#pragma unroll
        for (int k = 0; k < 4; k++)
            LDSM4(A[k], a_base + (uint32_t)(((k * 2 + lchk) ^ swrow) << 4));
    }

    float run_max[2], run_sum[2], diagv[2];
#pragma unroll
    for (int j = 0; j < 2; j++) {
        run_max[j] = -INFINITY; run_sum[j] = 0.0f; diagv[j] = 0.0f;
    }

    for (int t = 0; t < NTILES; t++) {
        const int s = t & 3;
        const int ph = (t >> 2) & 1;
        MBAR_WAIT(sb + BARO + s * 8, ph);

        float acc[8][4];
        const uint32_t th_base = sb + TBUF(s) + (uint32_t)(wc * 64 + lrow) * 128u;

#pragma unroll
        for (int k = 0; k < 4; k++) {
            const uint32_t sw = (uint32_t)(((k * 2 + lchk) ^ swrow) << 4);
            uint32_t B[4][4];
#pragma unroll
            for (int g = 0; g < 4; g++)
                LDSM4(B[g], th_base + (uint32_t)(g * 2048) + sw);
            if (k == 0) {
#pragma unroll
                for (int g = 0; g < 4; g++) {
                    MMA16816Z(acc[g * 2],     A[0], B[g][0], B[g][2]);
                    MMA16816Z(acc[g * 2 + 1], A[0], B[g][1], B[g][3]);
                }
            } else {
#pragma unroll
                for (int g = 0; g < 4; g++) {
                    MMA16816(acc[g * 2],     A[k], B[g][0], B[g][2]);
                    MMA16816(acc[g * 2 + 1], A[k], B[g][1], B[g][3]);
                }
            }
        }

        if (lane == 0) MBAR_ARRIVE(sb + BARO + 32 + s * 8);

        // ---- diagonal extraction (tile t == blockIdx.x) ----
        if (t == b) {
#pragma unroll
            for (int j = 0; j < 2; j++) {
                const int rloc = wr * 16 + j * 8 + (lane >> 2);
                const int cw = rloc - wc * 64;
                if (cw >= 0 && cw < 64) {
                    const int nt = cw >> 3;
                    if (((cw >> 1) & 3) == (lane & 3))
                        diagv[j] = acc[nt][j * 2 + (cw & 1)];
                }
            }
        }

        // ---- online softmax with adaptive skip ----
#pragma unroll
        for (int j = 0; j < 2; j++) {
            const int er = j * 2;
            float m8[8];
#pragma unroll
            for (int nt = 0; nt < 8; nt++)
                m8[nt] = fmaxf(acc[nt][er], acc[nt][er + 1]);
#pragma unroll
            for (int w = 4; w > 0; w >>= 1)
#pragma unroll
                for (int i = 0; i < w; i++) m8[i] = fmaxf(m8[i], m8[i + w]);
            float m = m8[0];
            m = fmaxf(m, __shfl_xor_sync(0xffffffffu, m, 1));
            m = fmaxf(m, __shfl_xor_sync(0xffffffffu, m, 2));

            const bool pass = (m > run_max[j] - SKIP_THRESH);
            if (__any_sync(0xffffffffu, pass)) {
                const float nm = fmaxf(run_max[j], m);
                float s0 = 0.f, s1 = 0.f;
#pragma unroll
                for (int nt = 0; nt < 8; nt++) {
                    s0 += __expf(acc[nt][er]     - nm);
                    s1 += __expf(acc[nt][er + 1] - nm);
                }
                float ss = s0 + s1;
                ss += __shfl_xor_sync(0xffffffffu, ss, 1);
                ss += __shfl_xor_sync(0xffffffffu, ss, 2);
                run_sum[j] = run_sum[j] * __expf(run_max[j] - nm) + ss;
                run_max[j] = nm;
            }
        }

        // refill stage s with tile t+4 after all 16 warps consumed it
        if (t + 4 < NTILES && tid == 0) {
            MBAR_WAIT(sb + BARO + 32 + s * 8, ph);
            MBAR_EXPECT(sb + BARO + s * 8, 16384);
            bulk_g2s(sb + TBUF(s), g_thf + (size_t)(t + 4) * 16384, 16384,
                     sb + BARO + s * 8);
        }
    }

    // ---- merge col-halves + block reduce ----
    __syncthreads();
    float* S = reinterpret_cast<float*>(smem);

#pragma unroll
    for (int j = 0; j < 2; j++) {
        float d = diagv[j];
        d += __shfl_xor_sync(0xffffffffu, d, 1);
        d += __shfl_xor_sync(0xffffffffu, d, 2);
        diagv[j] = d;
    }
    if ((lane & 3) == 0) {
#pragma unroll
        for (int j = 0; j < 2; j++) {
            const int r = wr * 16 + j * 8 + (lane >> 2);
            S[wc * 128 + r]       = run_max[j];
            S[256 + wc * 128 + r] = run_sum[j];
            S[512 + wc * 128 + r] = diagv[j];
        }
    }
    __syncthreads();

    float loss = 0.0f;
    if (tid < 128) {
        const float m0 = S[tid],       s0 = S[256 + tid], d0 = S[512 + tid];
        const float m1 = S[128 + tid], s1 = S[384 + tid], d1 = S[640 + tid];
        const float m = fmaxf(m0, m1);
        const float ssum = s0 * __expf(m0 - m) + s1 * __expf(m1 - m);
        loss = m + logf(ssum) - (d0 + d1);
    }
#pragma unroll
    for (int o = 16; o > 0; o >>= 1)
        loss += __shfl_xor_sync(0xffffffffu, loss, o);
    __syncthreads();
    if (lane == 0) S[768 + wid] = loss;
    __syncthreads();

    // ---- fused finalize: last block reduces all partials ----
    __shared__ unsigned int ticket;
    if (tid == 0) {
        float v = 0.0f;
#pragma unroll
        for (int i = 0; i < 16; i++) v += S[768 + i];
        g_partial[b] = v;
        __threadfence();
        ticket = atomicAdd(&g_done, 1u);
    }
    __syncthreads();
    if (ticket == NBLOCKS - 1) {
        __threadfence();
        float v = (tid < NBLOCKS) ? g_partial[tid] : 0.0f;
#pragma unroll
        for (int o = 16; o > 0; o >>= 1)
            v += __shfl_xor_sync(0xffffffffu, v, o);
        if (lane == 0) S[800 + wid] = v;
        __syncthreads();
        if (tid == 0) {
            float r = 0.0f;
#pragma unroll
            for (int i = 0; i < 16; i++) r += S[800 + i];
            out[0] = r / (float)NTOT;
            g_done = 0;
        }
    }
}

extern "C" void kernel_launch(void* const* d_in, const int* in_sizes, int n_in,
                              void* d_out, int out_size) {
    const float* logits  = (const float*)d_in[0];
    const float* targets = (const float*)d_in[1];
    const float* noise   = (const float*)d_in[2];

    cudaFuncSetAttribute(infonce_mma, cudaFuncAttributeMaxDynamicSharedMemorySize, SMEM_BYTES);

    prep_targets<<<NTOT * 8 / 256, 256>>>(targets);
    infonce_mma<<<NBLOCKS, NTHREADS, SMEM_BYTES>>>(logits, noise, (float*)d_out);
}

// round 7
// speedup vs baseline: 9.9263x; 1.2464x over previous
#include <cuda_runtime.h>
#include <cuda_fp16.h>
#include <math.h>
#include <stdint.h>

// loss = mean_n [ logsumexp_m( q_n . t_m ) - q_n . t_n ],  q = logits - log(noise)
// N = M = 16384, D = 64.
// Single-term fp16 mma.sync; 4x4 warp grid (32x32 warp tiles) halves B-LDSM
// duplication; per-lane online sums with quad-shared max (no sum-shuffles in
// the loop); adaptive exp skipping; 4-deep cp.async.bulk tile ring.

#define NTOT    16384
#define DIM     64
#define TM      128                 // q rows per block
#define TN      128                 // target rows per tile iteration
#define NTILES  (NTOT / TN)         // 128
#define NBLOCKS (NTOT / TM)         // 128
#define NTHREADS 512
#define SKIP_THRESH 13.0f

__device__ __align__(128) unsigned char g_thf[(size_t)NTOT * 128];
__device__ float g_partial[NBLOCKS];
__device__ unsigned int g_done;

// ---------------- PTX helpers ----------------
static __device__ __forceinline__ uint32_t smem_u32(const void* p) {
    uint32_t a;
    asm("{ .reg .u64 t; cvta.to.shared.u64 t, %1; cvt.u32.u64 %0, t; }"
        : "=r"(a) : "l"(p));
    return a;
}
#define MBAR_INIT(a, c) \
    asm volatile("mbarrier.init.shared.b64 [%0], %1;" :: "r"(a), "r"(c) : "memory")
#define MBAR_EXPECT(a, b) \
    asm volatile("mbarrier.arrive.expect_tx.shared.b64 _, [%0], %1;" :: "r"(a), "r"(b) : "memory")
#define MBAR_ARRIVE(a) \
    asm volatile("mbarrier.arrive.shared.b64 _, [%0];" :: "r"(a) : "memory")
#define MBAR_WAIT(a, ph) do {                                                        \
    uint32_t _m = (a), _p = (ph), _d;                                                \
    asm volatile("{ .reg .pred p; mbarrier.try_wait.parity.acquire.cta.shared::cta.b64 p, [%1], %2; selp.b32 %0,1,0,p; }" \
                 : "=r"(_d) : "r"(_m), "r"(_p) : "memory");                          \
    if (!_d) {                                                                       \
        asm volatile("{ .reg .pred P1; WL%=: mbarrier.try_wait.parity.acquire.cta.shared::cta.b64 P1, [%0], %1, 0x989680; @P1 bra.uni WD%=; bra.uni WL%=; WD%=: }" \
                     :: "r"(_m), "r"(_p) : "memory");                                \
    }                                                                                \
} while (0)

static __device__ __forceinline__ void bulk_g2s(uint32_t dst, const void* src,
                                                uint32_t bytes, uint32_t mbar) {
    uint64_t g;
    asm("cvta.to.global.u64 %0, %1;" : "=l"(g) : "l"(src));
    asm volatile("cp.async.bulk.shared::cta.global.mbarrier::complete_tx::bytes [%0], [%1], %2, [%3];"
                 :: "r"(dst), "l"(g), "r"(bytes), "r"(mbar) : "memory");
}

#define LDSM4(r, a) \
    asm volatile("ldmatrix.sync.aligned.m8n8.x4.shared.b16 {%0,%1,%2,%3}, [%4];" \
                 : "=r"((r)[0]), "=r"((r)[1]), "=r"((r)[2]), "=r"((r)[3]) : "r"(a))

#define MMA16816(d, a, b0, b1) \
    asm volatile("mma.sync.aligned.m16n8k16.row.col.f32.f16.f16.f32 " \
                 "{%0,%1,%2,%3}, {%4,%5,%6,%7}, {%8,%9}, {%0,%1,%2,%3};" \
                 : "+f"((d)[0]), "+f"((d)[1]), "+f"((d)[2]), "+f"((d)[3]) \
                 : "r"((a)[0]), "r"((a)[1]), "r"((a)[2]), "r"((a)[3]), \
                   "r"(b0), "r"(b1))

#define MMA16816Z(d, a, b0, b1) \
    asm volatile("mma.sync.aligned.m16n8k16.row.col.f32.f16.f16.f32 " \
                 "{%0,%1,%2,%3}, {%4,%5,%6,%7}, {%8,%9}, {%10,%10,%10,%10};" \
                 : "=f"((d)[0]), "=f"((d)[1]), "=f"((d)[2]), "=f"((d)[3]) \
                 : "r"((a)[0]), "r"((a)[1]), "r"((a)[2]), "r"((a)[3]), \
                   "r"(b0), "r"(b1), "f"(0.0f))

static __device__ __forceinline__ uint32_t pack_h2(float a, float b) {
    __half2 h = __floats2half2_rn(a, b);
    return *reinterpret_cast<uint32_t*>(&h);
}

// ---------------- prep: convert + swizzle targets into fp16 image ----------------
__global__ void __launch_bounds__(256) prep_targets(const float* __restrict__ tg) {
    int idx = blockIdx.x * 256 + threadIdx.x;
    int row = idx >> 3, c = idx & 7;
    const float4* p = reinterpret_cast<const float4*>(tg + (size_t)row * DIM + c * 8);
    float4 a = p[0], b = p[1];
    uint4 u = make_uint4(pack_h2(a.x, a.y), pack_h2(a.z, a.w),
                         pack_h2(b.x, b.y), pack_h2(b.z, b.w));
    int slot = row * 8 + (c ^ (row & 7));
    reinterpret_cast<uint4*>(g_thf)[slot] = u;
}

// SMEM: [0,16K) q fp16, [16K + s*16K) tile ring s=0..3, [80K) mbarriers
#define QOFF  0u
#define TBUF(s) (16384u + (uint32_t)(s) * 16384u)
#define BARO  81920u
#define SMEM_BYTES (81920 + 128)

__global__ void __launch_bounds__(NTHREADS, 1)
infonce_mma(const float* __restrict__ logits, const float* __restrict__ noise,
            float* __restrict__ out) {
    extern __shared__ unsigned char smem[];
    const uint32_t sb = smem_u32(smem);
    const int tid = threadIdx.x, wid = tid >> 5, lane = tid & 31;
    const int b = blockIdx.x;

    if (tid == 0) {
#pragma unroll
        for (int s = 0; s < 4; s++) {
            MBAR_INIT(sb + BARO + s * 8, 1);        // data ready
            MBAR_INIT(sb + BARO + 32 + s * 8, 16);  // consumed (16 warps)
        }
    }

    // ---- q prologue: q = logits - log(noise) -> fp16, swizzled ----
#pragma unroll
    for (int i = 0; i < 2; i++) {
        int ch = tid + NTHREADS * i;            // 0..1023 (128 rows x 8 chunks)
        int row = ch >> 3, c = ch & 7;
        const float4* p = reinterpret_cast<const float4*>(
            logits + (size_t)(b * TM + row) * DIM + c * 8);
        float4 a = p[0], bb = p[1];
        float x[8] = {a.x, a.y, a.z, a.w, bb.x, bb.y, bb.z, bb.w};
#pragma unroll
        for (int j = 0; j < 8; j++) x[j] -= logf(noise[c * 8 + j]);
        uint4 u = make_uint4(pack_h2(x[0], x[1]), pack_h2(x[2], x[3]),
                             pack_h2(x[4], x[5]), pack_h2(x[6], x[7]));
        uint32_t off = (uint32_t)row * 128u + (uint32_t)((c ^ (row & 7)) * 16);
        *reinterpret_cast<uint4*>(smem + QOFF + off) = u;
    }

    if (tid == 0) {
#pragma unroll
        for (int s = 0; s < 4; s++) {
            MBAR_EXPECT(sb + BARO + s * 8, 16384);
            bulk_g2s(sb + TBUF(s), g_thf + (size_t)s * 16384, 16384, sb + BARO + s * 8);
        }
    }
    __syncthreads();

    // warp grid: 4 row-groups x 4 col-groups; warp tile = 32 rows x 32 cols
    const int wr = wid & 3, wc = wid >> 2;
    const int lrow  = lane & 15;
    const int lchk  = lane >> 4;
    const int swrow = lane & 7;

    // hoisted swizzle offsets per k-step
    uint32_t swk[4];
#pragma unroll
    for (int k = 0; k < 4; k++)
        swk[k] = (uint32_t)(((k * 2 + lchk) ^ swrow) << 4);

    // ---- preload A (q) fragments: tile-invariant (2 m-tiles x 4 k-steps) ----
    uint32_t A[2][4][4];
#pragma unroll
    for (int mt = 0; mt < 2; mt++) {
        const uint32_t a_base = sb + QOFF +
            (uint32_t)(wr * 32 + mt * 16 + lrow) * 128u;
#pragma unroll
        for (int k = 0; k < 4; k++)
            LDSM4(A[mt][k], a_base + swk[k]);
    }

    const uint32_t woff = (uint32_t)(wc * 32 + lrow) * 128u;

    // per-lane sums, quad-shared maxes; j = mt*2 + e  (4 row-groups / thread)
    float run_max[4], run_sum[4], diagv[4];
#pragma unroll
    for (int j = 0; j < 4; j++) {
        run_max[j] = -INFINITY; run_sum[j] = 0.0f; diagv[j] = 0.0f;
    }

    for (int t = 0; t < NTILES; t++) {
        const int s = t & 3;
        const int ph = (t >> 2) & 1;
        MBAR_WAIT(sb + BARO + s * 8, ph);

        float acc[8][4];                         // [mt*4 + nt][e]
        const uint32_t th_base = sb + TBUF(s) + woff;

#pragma unroll
        for (int k = 0; k < 4; k++) {
            uint32_t B[2][4];
            LDSM4(B[0], th_base + swk[k]);
            LDSM4(B[1], th_base + 2048u + swk[k]);
            if (k == 0) {
#pragma unroll
                for (int mt = 0; mt < 2; mt++)
#pragma unroll
                    for (int nt = 0; nt < 4; nt++) {
                        const int g = nt >> 1, su = nt & 1;
                        MMA16816Z(acc[mt * 4 + nt], A[mt][0], B[g][su], B[g][2 + su]);
                    }
            } else {
#pragma unroll
                for (int mt = 0; mt < 2; mt++)
#pragma unroll
                    for (int nt = 0; nt < 4; nt++) {
                        const int g = nt >> 1, su = nt & 1;
                        MMA16816(acc[mt * 4 + nt], A[mt][k], B[g][su], B[g][2 + su]);
                    }
            }
        }

        if (lane == 0) MBAR_ARRIVE(sb + BARO + 32 + s * 8);

        // ---- diagonal extraction (tile t == blockIdx.x) ----
        if (t == b) {
#pragma unroll
            for (int j = 0; j < 4; j++) {
                const int mt = j >> 1, e = j & 1;
                const int rloc = wr * 32 + mt * 16 + e * 8 + (lane >> 2);
                const int cw = rloc - wc * 32;
                if (cw >= 0 && cw < 32) {
                    const int nt = cw >> 3;
                    if (((cw >> 1) & 3) == (lane & 3))
                        diagv[j] = acc[mt * 4 + nt][e * 2 + (cw & 1)];
                }
            }
        }

        // ---- online softmax: quad-shared max, per-lane sums ----
#pragma unroll
        for (int j = 0; j < 4; j++) {
            const int mt = j >> 1, er = (j & 1) * 2;
            float m4[4];
#pragma unroll
            for (int nt = 0; nt < 4; nt++)
                m4[nt] = fmaxf(acc[mt * 4 + nt][er], acc[mt * 4 + nt][er + 1]);
            m4[0] = fmaxf(m4[0], m4[2]);
            m4[1] = fmaxf(m4[1], m4[3]);
            float m = fmaxf(m4[0], m4[1]);
            m = fmaxf(m, __shfl_xor_sync(0xffffffffu, m, 1));
            m = fmaxf(m, __shfl_xor_sync(0xffffffffu, m, 2));   // row-uniform

            const bool pass = (m > run_max[j] - SKIP_THRESH);
            if (__any_sync(0xffffffffu, pass)) {
                const float nm = fmaxf(run_max[j], m);
                float s0 = 0.f, s1 = 0.f;
#pragma unroll
                for (int nt = 0; nt < 4; nt++) {
                    s0 += __expf(acc[mt * 4 + nt][er]     - nm);
                    s1 += __expf(acc[mt * 4 + nt][er + 1] - nm);
                }
                run_sum[j] = run_sum[j] * __expf(run_max[j] - nm) + (s0 + s1);
                run_max[j] = nm;
            }
        }

        if (t + 4 < NTILES && tid == 0) {
            MBAR_WAIT(sb + BARO + 32 + s * 8, ph);
            MBAR_EXPECT(sb + BARO + s * 8, 16384);
            bulk_g2s(sb + TBUF(s), g_thf + (size_t)(t + 4) * 16384, 16384,
                     sb + BARO + s * 8);
        }
    }

    // ---- quad merges (sum + diag), then block reduce over 4 col-groups ----
    __syncthreads();
    float* S = reinterpret_cast<float*>(smem);   // 3 arrays of 512 floats

#pragma unroll
    for (int j = 0; j < 4; j++) {
        float ss = run_sum[j];
        ss += __shfl_xor_sync(0xffffffffu, ss, 1);
        ss += __shfl_xor_sync(0xffffffffu, ss, 2);
        run_sum[j] = ss;                          // max already quad-uniform
        float d = diagv[j];
        d += __shfl_xor_sync(0xffffffffu, d, 1);
        d += __shfl_xor_sync(0xffffffffu, d, 2);
        diagv[j] = d;
    }
    if ((lane & 3) == 0) {
#pragma unroll
        for (int j = 0; j < 4; j++) {
            const int mt = j >> 1, e = j & 1;
            const int r = wr * 32 + mt * 16 + e * 8 + (lane >> 2);
            S[wc * 128 + r]        = run_max[j];
            S[512 + wc * 128 + r]  = run_sum[j];
            S[1024 + wc * 128 + r] = diagv[j];
        }
    }
    __syncthreads();

    float loss = 0.0f;
    if (tid < 128) {
        float m = S[tid];
#pragma unroll
        for (int g = 1; g < 4; g++) m = fmaxf(m, S[g * 128 + tid]);
        float ssum = 0.0f, d = 0.0f;
#pragma unroll
        for (int g = 0; g < 4; g++) {
            ssum += S[512 + g * 128 + tid] * __expf(S[g * 128 + tid] - m);
            d    += S[1024 + g * 128 + tid];
        }
        loss = m + logf(ssum) - d;
    }
#pragma unroll
    for (int o = 16; o > 0; o >>= 1)
        loss += __shfl_xor_sync(0xffffffffu, loss, o);
    __syncthreads();
    if (lane == 0) S[1536 + wid] = loss;
    __syncthreads();

    // ---- fused finalize: last block reduces all partials ----
    __shared__ unsigned int ticket;
    if (tid == 0) {
        float v = 0.0f;
#pragma unroll
        for (int i = 0; i < 16; i++) v += S[1536 + i];
        g_partial[b] = v;
        __threadfence();
        ticket = atomicAdd(&g_done, 1u);
    }
    __syncthreads();
    if (ticket == NBLOCKS - 1) {
        __threadfence();
        float v = (tid < NBLOCKS) ? g_partial[tid] : 0.0f;
#pragma unroll
        for (int o = 16; o > 0; o >>= 1)
            v += __shfl_xor_sync(0xffffffffu, v, o);
        if (lane == 0) S[1600 + wid] = v;
        __syncthreads();
        if (tid == 0) {
            float r = 0.0f;
#pragma unroll
            for (int i = 0; i < 16; i++) r += S[1600 + i];
            out[0] = r / (float)NTOT;
            g_done = 0;
        }
    }
}

extern "C" void kernel_launch(void* const* d_in, const int* in_sizes, int n_in,
                              void* d_out, int out_size) {
    const float* logits  = (const float*)d_in[0];
    const float* targets = (const float*)d_in[1];
    const float* noise   = (const float*)d_in[2];

    cudaFuncSetAttribute(infonce_mma, cudaFuncAttributeMaxDynamicSharedMemorySize, SMEM_BYTES);

    prep_targets<<<NTOT * 8 / 256, 256>>>(targets);
    infonce_mma<<<NBLOCKS, NTHREADS, SMEM_BYTES>>>(logits, noise, (float*)d_out);
}